// round 14
// baseline (speedup 1.0000x reference)
#include <cuda_runtime.h>
#include <cuda_bf16.h>
#include <cuda_fp16.h>
#include <cstdint>
#include <cstddef>

// ---------------------------------------------------------------------------
// Shapes: B=512, LATENT=LOCAL=256, HIDDEN=512, HW=256
// out[k][i][j] = sum_c pred[i][c] * positive[j][c][k]  - rowmax_j
// R14: plain fp16 HMMA (K=256). CTA = 64i x 512j, 512 threads (16 warps =
// 8 j-groups x 2 i-halves), 1 CTA/SM. B slice pair-shared: each warp of a
// j-group loads half the rows into a shared 3-stage ring; pair syncs via
// named barrier (no CTA-wide barriers in the mainloop). B L2 traffic halves
// (1 GB -> 512 MB) vs the 32i layout.
// ---------------------------------------------------------------------------

#define BSZ     512
#define LATENT  256
#define HIDDEN  512
#define HW      256
#define KP      256
#define NCHUNK  (KP / 32)        // 8

__device__ float   g_h[BSZ * HIDDEN];
__device__ float   g_a[BSZ * LATENT];
__device__ __half  g_predX[BSZ * KP];                 // 256 KB
__device__ __half  g_posX[(size_t)HW * BSZ * KP];     // 64 MB (fits in L2)

// ---------------------------------------------------------------------------
// PTX helpers (generic-target only: cp.async, ldmatrix, mma.sync)
// ---------------------------------------------------------------------------
__device__ __forceinline__ uint32_t smem_u32(const void* p) {
    uint32_t a;
    asm("{ .reg .u64 t; cvta.to.shared.u64 t, %1; cvt.u32.u64 %0, t; }"
        : "=r"(a) : "l"(p));
    return a;
}
__device__ __forceinline__ void cp16(uint32_t dst, const void* src) {
    asm volatile("cp.async.cg.shared.global [%0], [%1], 16;"
                 :: "r"(dst), "l"(src) : "memory");
}
#define CP_COMMIT() asm volatile("cp.async.commit_group;" ::: "memory")
#define CP_WAIT(N)  asm volatile("cp.async.wait_group %0;" :: "n"(N) : "memory")
#define BAR_SYNC(id, cnt) \
    asm volatile("bar.sync %0, %1;" :: "r"(id), "r"(cnt) : "memory")

__device__ __forceinline__ void ldmx4(uint32_t& r0, uint32_t& r1,
                                      uint32_t& r2, uint32_t& r3,
                                      uint32_t addr) {
    asm volatile("ldmatrix.sync.aligned.m8n8.x4.shared.b16 {%0,%1,%2,%3}, [%4];"
                 : "=r"(r0), "=r"(r1), "=r"(r2), "=r"(r3) : "r"(addr));
}
__device__ __forceinline__ void mma16816(float* c,
                                         uint32_t a0, uint32_t a1,
                                         uint32_t a2, uint32_t a3,
                                         uint32_t b0, uint32_t b1) {
    asm volatile("mma.sync.aligned.m16n8k16.row.col.f32.f16.f16.f32 "
                 "{%0,%1,%2,%3}, {%4,%5,%6,%7}, {%8,%9}, {%0,%1,%2,%3};"
                 : "+f"(c[0]), "+f"(c[1]), "+f"(c[2]), "+f"(c[3])
                 : "r"(a0), "r"(a1), "r"(a2), "r"(a3), "r"(b0), "r"(b1));
}

// SW128 over 64B logical rows: row r, quad q (16B units, q=0..3).
__device__ __forceinline__ uint32_t swz(uint32_t r, uint32_t q) {
    uint32_t R = r >> 1;
    uint32_t c = (q + ((r & 1) << 2)) ^ (R & 7);
    return R * 128 + c * 16;
}

// ---------------------------------------------------------------------------
// Small fp32 GEMM for the MLP chain; optional fp16 output (Ch != nullptr)
// ---------------------------------------------------------------------------
__global__ void __launch_bounds__(256)
gemm_tile(const float* __restrict__ A, const float* __restrict__ B,
          const float* __restrict__ bias, const float* __restrict__ res,
          float* __restrict__ C, __half* __restrict__ Ch,
          int M, int N, int K, int doRelu)
{
    __shared__ float As[16][64];
    __shared__ float Bs[16][64];

    const int tid = threadIdx.x;
    const int tig = tid >> 4, tjg = tid & 15;
    const int m0 = blockIdx.y * 64, n0 = blockIdx.x * 64;
    const int arow = tid >> 2, aq = tid & 3;
    const int brow = tid >> 4, bq = tid & 15;

    float acc[4][4] = {};

    for (int kk = 0; kk < K; kk += 16) {
        float4 av = *(const float4*)(A + (size_t)(m0 + arow) * K + kk + aq * 4);
        float4 bv = *(const float4*)(B + (size_t)(kk + brow) * N + n0 + bq * 4);
        __syncthreads();
        As[aq * 4 + 0][arow] = av.x; As[aq * 4 + 1][arow] = av.y;
        As[aq * 4 + 2][arow] = av.z; As[aq * 4 + 3][arow] = av.w;
        *(float4*)&Bs[brow][bq * 4] = bv;
        __syncthreads();
#pragma unroll
        for (int kc = 0; kc < 16; ++kc) {
            float4 a = *(const float4*)&As[kc][tig * 4];
            float4 b = *(const float4*)&Bs[kc][tjg * 4];
            acc[0][0] = fmaf(a.x, b.x, acc[0][0]); acc[0][1] = fmaf(a.x, b.y, acc[0][1]);
            acc[0][2] = fmaf(a.x, b.z, acc[0][2]); acc[0][3] = fmaf(a.x, b.w, acc[0][3]);
            acc[1][0] = fmaf(a.y, b.x, acc[1][0]); acc[1][1] = fmaf(a.y, b.y, acc[1][1]);
            acc[1][2] = fmaf(a.y, b.z, acc[1][2]); acc[1][3] = fmaf(a.y, b.w, acc[1][3]);
            acc[2][0] = fmaf(a.z, b.x, acc[2][0]); acc[2][1] = fmaf(a.z, b.y, acc[2][1]);
            acc[2][2] = fmaf(a.z, b.z, acc[2][2]); acc[2][3] = fmaf(a.z, b.w, acc[2][3]);
            acc[3][0] = fmaf(a.w, b.x, acc[3][0]); acc[3][1] = fmaf(a.w, b.y, acc[3][1]);
            acc[3][2] = fmaf(a.w, b.z, acc[3][2]); acc[3][3] = fmaf(a.w, b.w, acc[3][3]);
        }
    }

#pragma unroll
    for (int r = 0; r < 4; ++r) {
        int gi = m0 + tig * 4 + r;
#pragma unroll
        for (int c = 0; c < 4; ++c) {
            int gj = n0 + tjg * 4 + c;
            float v = acc[r][c];
            if (bias) v += bias[gj];
            if (res)  v += res[(size_t)gi * N + gj];
            if (doRelu) v = fmaxf(v, 0.0f);
            if (Ch) Ch[(size_t)gi * N + gj] = __float2half(v);
            else    C [(size_t)gi * N + gj] = v;
        }
    }
}

// ---------------------------------------------------------------------------
// posX[k][j][c] = fp16(positive[j][c][k])  (transpose + convert)
// Tile 64r x 32k; 16B vectorized stores (full 128B sectors).
// ---------------------------------------------------------------------------
__global__ void __launch_bounds__(256)
possplit_kernel(const float* __restrict__ in, __half* __restrict__ out)
{
    __shared__ float tile[64][33];
    const int rbase = blockIdx.x * 64;
    const int kbase = blockIdx.y * 32;
    const int tx = threadIdx.x & 31, ty = threadIdx.x >> 5;

#pragma unroll
    for (int m = 0; m < 8; ++m) {
        int r = rbase + ty + m * 8;
        tile[ty + m * 8][tx] = __ldcs(&in[(size_t)r * 256 + kbase + tx]);
    }
    __syncthreads();

    const int t   = threadIdx.x;
    const int kk  = t >> 3;
    const int rr0 = (t & 7) * 8;
    const int k   = kbase + kk;
    const int rg  = rbase + rr0;
    const int j   = rg >> 8, c = rg & 255;

    __half h[8];
#pragma unroll
    for (int e = 0; e < 8; ++e) h[e] = __float2half(tile[rr0 + e][kk]);
    *(uint4*)&out[((size_t)k * BSZ + j) * KP + c] = *(const uint4*)h;
}

// ---------------------------------------------------------------------------
// HMMA contrast kernel v4. CTA = (k, 64-row i-tile), full j=512, K=256.
// 512 threads, 16 warps = 8 j-groups x 2 i-halves. A preloaded (32KB,
// 8 chunks x 4KB). Per j-group: shared 3-stage B ring (4KB stages), each
// warp of the pair loads 32 of the 64 rows; pair syncs via named barrier.
// ---------------------------------------------------------------------------
#define OF_BSL   32768                   // B rings after A region
#define CT_SMEM  (32768 + 8 * 3 * 4096)  // 131072 -> 1 CTA/SM

__global__ void __launch_bounds__(512, 1)
contrast_mma(const __half* __restrict__ predX,
             const __half* __restrict__ posX,
             float* __restrict__ out)
{
    extern __shared__ char smem[];
    const uint32_t sb = smem_u32(smem);
    const int tid = threadIdx.x;
    const int wid = tid >> 5, lid = tid & 31;
    const int k  = blockIdx.x >> 3;
    const int i0 = (blockIdx.x & 7) << 6;

    const int jg = wid >> 1;             // j-group 0..7
    const int ih = wid & 1;              // i-half 0..1

    const char* Ab = (const char*)(predX + (size_t)i0 * KP);
    const char* Bw = (const char*)(posX + ((size_t)k * BSZ + jg * 64) * KP);

    float acc[16][4];   // tile t = mi*8 + njp*2 + hb
#pragma unroll
    for (int t = 0; t < 16; ++t) {
        acc[t][0] = 0.f; acc[t][1] = 0.f; acc[t][2] = 0.f; acc[t][3] = 0.f;
    }

    // ---- prologue: load ALL of A (64 rows x 256 K = 32KB, 8 chunk blocks)
    {
        const int half = tid >> 8, h = tid & 255;
        const int r = h >> 2, q = h & 3;
#pragma unroll
        for (int p = 0; p < 4; ++p) {
            const int ch = p * 2 + half;
            cp16(sb + ch * 4096 + swz(r, q),
                 Ab + (size_t)r * (KP * 2) + ch * 64 + q * 16);
        }
        CP_COMMIT();                     // group: A
    }

    // ---- pair-shared B loader: this warp loads rows [ih*32, ih*32+32) ----
    const int bl_r = ih * 32 + (lid >> 2), bl_q = lid & 3;
    const uint32_t sbB = sb + OF_BSL + jg * (3 * 4096);
    auto loadB = [&](int n) {
        const uint32_t st = sbB + (n % 3) * 4096;
        const size_t co = (size_t)n * 64 + bl_q * 16;
#pragma unroll
        for (int it = 0; it < 4; ++it) {
            const int row = bl_r + it * 8;
            cp16(st + swz(row, bl_q), Bw + (size_t)row * (KP * 2) + co);
        }
        CP_COMMIT();
    };

    loadB(0);
    loadB(1);
    CP_WAIT(2);          // groups retire in order: A complete
    __syncthreads();     // A visible CTA-wide

    const uint32_t lrow = (uint32_t)(lid & 15);
    const uint32_t lqq  = (uint32_t)(lid >> 4);

#pragma unroll 1
    for (int n = 0; n < NCHUNK; ++n) {
        CP_WAIT(1);                 // own half of chunk n resident
        BAR_SYNC(jg + 1, 64);       // pair rendezvous: full slice resident,
                                    // both warps past chunk n-1
        if (n + 2 < NCHUNK) loadB(n + 2);

        const uint32_t at = sb + n * 4096;
        const uint32_t bt = sbB + (n % 3) * 4096;

        // A fragments for this chunk (both ks halves, this warp's i-half)
        uint32_t a[2][2][4];
#pragma unroll
        for (int ks = 0; ks < 2; ++ks)
#pragma unroll
            for (int mi = 0; mi < 2; ++mi)
                ldmx4(a[ks][mi][0], a[ks][mi][1], a[ks][mi][2], a[ks][mi][3],
                      at + swz(ih * 32 + mi * 16 + lrow, ks * 2 + lqq));

        // B fragments double-buffered across the 8 (ks,njp) steps
        uint32_t b[2][4];
        ldmx4(b[0][0], b[0][1], b[0][2], b[0][3], bt + swz(lrow, lqq));
#pragma unroll
        for (int f = 0; f < 8; ++f) {
            const int ks = f >> 2, njp = f & 3;
            if (f < 7) {
                const int g = f + 1, gks = g >> 2, gnjp = g & 3;
                ldmx4(b[g & 1][0], b[g & 1][1], b[g & 1][2], b[g & 1][3],
                      bt + swz(gnjp * 16 + lrow, gks * 2 + lqq));
            }
            const uint32_t* bb = b[f & 1];
#pragma unroll
            for (int mi = 0; mi < 2; ++mi) {
                mma16816(acc[mi * 8 + njp * 2 + 0],
                         a[ks][mi][0], a[ks][mi][1], a[ks][mi][2], a[ks][mi][3],
                         bb[0], bb[2]);
                mma16816(acc[mi * 8 + njp * 2 + 1],
                         a[ks][mi][0], a[ks][mi][1], a[ks][mi][2], a[ks][mi][3],
                         bb[1], bb[3]);
            }
        }
    }

    // ---- fused row-max: warp covers 32 i rows (its half), distinct j ----
    float mx0[2], mx1[2];
#pragma unroll
    for (int mi = 0; mi < 2; ++mi) {
        mx0[mi] = -3.402823466e38f;
        mx1[mi] = -3.402823466e38f;
#pragma unroll
        for (int nj = 0; nj < 8; ++nj) {
            const float* c = acc[mi * 8 + nj];
            mx0[mi] = fmaxf(mx0[mi], fmaxf(c[0], c[1]));
            mx1[mi] = fmaxf(mx1[mi], fmaxf(c[2], c[3]));
        }
        mx0[mi] = fmaxf(mx0[mi], __shfl_xor_sync(0xffffffffu, mx0[mi], 1));
        mx0[mi] = fmaxf(mx0[mi], __shfl_xor_sync(0xffffffffu, mx0[mi], 2));
        mx1[mi] = fmaxf(mx1[mi], __shfl_xor_sync(0xffffffffu, mx1[mi], 1));
        mx1[mi] = fmaxf(mx1[mi], __shfl_xor_sync(0xffffffffu, mx1[mi], 2));
    }

    __syncthreads();                 // ALL warps done with mainloop SMEM
    float* rmax = (float*)smem;      // reuse A region: [8 jg][64 i-rows]
    const int tr = lid >> 2;         // 0..7
    if ((lid & 3) == 0) {
#pragma unroll
        for (int mi = 0; mi < 2; ++mi) {
            rmax[jg * 64 + ih * 32 + mi * 16 + tr]     = mx0[mi];
            rmax[jg * 64 + ih * 32 + mi * 16 + 8 + tr] = mx1[mi];
        }
    }
    __syncthreads();

    float m0[2], m1[2];
#pragma unroll
    for (int mi = 0; mi < 2; ++mi) {
        float a0 = -3.402823466e38f, a1 = -3.402823466e38f;
        const int r0 = ih * 32 + mi * 16 + tr;
#pragma unroll
        for (int w = 0; w < 8; ++w) {
            a0 = fmaxf(a0, rmax[w * 64 + r0]);
            a1 = fmaxf(a1, rmax[w * 64 + r0 + 8]);
        }
        m0[mi] = a0; m1[mi] = a1;
    }

    // ---- subtract + streaming store (evict-first: keep posX resident) ----
    const size_t obase =
        ((size_t)k * BSZ + i0 + ih * 32) * BSZ + jg * 64 + (lid & 3) * 2;
#pragma unroll
    for (int mi = 0; mi < 2; ++mi) {
        float* o0 = out + obase + (size_t)(mi * 16 + tr) * BSZ;
        float* o1 = o0 + (size_t)8 * BSZ;
#pragma unroll
        for (int nj = 0; nj < 8; ++nj) {
            const float* c = acc[mi * 8 + nj];
            __stcs((float2*)(o0 + nj * 8), make_float2(c[0] - m0[mi], c[1] - m0[mi]));
            __stcs((float2*)(o1 + nj * 8), make_float2(c[2] - m1[mi], c[3] - m1[mi]));
        }
    }
}

// ---------------------------------------------------------------------------
// Launch
// ---------------------------------------------------------------------------
extern "C" void kernel_launch(void* const* d_in, const int* in_sizes, int n_in,
                              void* d_out, int out_size)
{
    const float* anchor   = (const float*)d_in[0];
    const float* positive = (const float*)d_in[1];
    const float* W1       = (const float*)d_in[2];
    const float* b1       = (const float*)d_in[3];
    const float* W2       = (const float*)d_in[4];
    const float* b2       = (const float*)d_in[5];
    const float* Wc       = (const float*)d_in[6];
    float* out            = (float*)d_out;

    float *hp, *ap;
    __half *px, *qx;
    cudaGetSymbolAddress((void**)&hp, g_h);
    cudaGetSymbolAddress((void**)&ap, g_a);
    cudaGetSymbolAddress((void**)&qx, g_predX);
    cudaGetSymbolAddress((void**)&px, g_posX);

    cudaFuncSetAttribute(contrast_mma,
                         cudaFuncAttributeMaxDynamicSharedMemorySize, CT_SMEM);

    // MLP chain (fp32); 3rd GEMM writes fp16 predX directly
    gemm_tile<<<dim3(HIDDEN / 64, BSZ / 64), 256>>>(
        anchor, W1, b1, nullptr, hp, nullptr, BSZ, HIDDEN, LATENT, 1);
    gemm_tile<<<dim3(LATENT / 64, BSZ / 64), 256>>>(
        hp, W2, b2, anchor, ap, nullptr, BSZ, LATENT, HIDDEN, 0);
    gemm_tile<<<dim3(LATENT / 64, BSZ / 64), 256>>>(
        ap, Wc, nullptr, nullptr, nullptr, qx, BSZ, LATENT, LATENT, 0);

    // fp16 transpose prep (vectorized stores)
    possplit_kernel<<<dim3((BSZ * 256) / 64, HW / 32), dim3(256)>>>(positive, px);

    // HMMA contrast GEMM + fused rowmax (64i CTAs, pair-shared B rings)
    contrast_mma<<<HW * 8, 512, CT_SMEM>>>(qx, px, out);
}

// round 15
// speedup vs baseline: 1.0927x; 1.0927x over previous
#include <cuda_runtime.h>
#include <cuda_bf16.h>
#include <cuda_fp16.h>
#include <cstdint>
#include <cstddef>

// ---------------------------------------------------------------------------
// Shapes: B=512, LATENT=LOCAL=256, HIDDEN=512, HW=256
// out[k][i][j] = sum_c pred[i][c] * positive[j][c][k]  - rowmax_j
// R15: R13 contrast (32i x 512j, 2 CTAs/SM, warp-private B rings) +
//   - MLP GEMMs retiled 64x64 -> 32x32 (256/128/128 CTAs: full chip width)
//   - contrast: loadB(n+2) issued BEFORE the cp.async wait (wait_group 2)
// ---------------------------------------------------------------------------

#define BSZ     512
#define LATENT  256
#define HIDDEN  512
#define HW      256
#define KP      256
#define NCHUNK  (KP / 32)        // 8

__device__ float   g_h[BSZ * HIDDEN];
__device__ float   g_a[BSZ * LATENT];
__device__ __half  g_predX[BSZ * KP];                 // 256 KB
__device__ __half  g_posX[(size_t)HW * BSZ * KP];     // 64 MB (fits in L2)

// ---------------------------------------------------------------------------
// PTX helpers (generic-target only: cp.async, ldmatrix, mma.sync)
// ---------------------------------------------------------------------------
__device__ __forceinline__ uint32_t smem_u32(const void* p) {
    uint32_t a;
    asm("{ .reg .u64 t; cvta.to.shared.u64 t, %1; cvt.u32.u64 %0, t; }"
        : "=r"(a) : "l"(p));
    return a;
}
__device__ __forceinline__ void cp16(uint32_t dst, const void* src) {
    asm volatile("cp.async.cg.shared.global [%0], [%1], 16;"
                 :: "r"(dst), "l"(src) : "memory");
}
#define CP_COMMIT() asm volatile("cp.async.commit_group;" ::: "memory")
#define CP_WAIT(N)  asm volatile("cp.async.wait_group %0;" :: "n"(N) : "memory")

__device__ __forceinline__ void ldmx4(uint32_t& r0, uint32_t& r1,
                                      uint32_t& r2, uint32_t& r3,
                                      uint32_t addr) {
    asm volatile("ldmatrix.sync.aligned.m8n8.x4.shared.b16 {%0,%1,%2,%3}, [%4];"
                 : "=r"(r0), "=r"(r1), "=r"(r2), "=r"(r3) : "r"(addr));
}
__device__ __forceinline__ void mma16816(float* c,
                                         uint32_t a0, uint32_t a1,
                                         uint32_t a2, uint32_t a3,
                                         uint32_t b0, uint32_t b1) {
    asm volatile("mma.sync.aligned.m16n8k16.row.col.f32.f16.f16.f32 "
                 "{%0,%1,%2,%3}, {%4,%5,%6,%7}, {%8,%9}, {%0,%1,%2,%3};"
                 : "+f"(c[0]), "+f"(c[1]), "+f"(c[2]), "+f"(c[3])
                 : "r"(a0), "r"(a1), "r"(a2), "r"(a3), "r"(b0), "r"(b1));
}

// SW128 over 64B logical rows: row r, quad q (16B units, q=0..3).
__device__ __forceinline__ uint32_t swz(uint32_t r, uint32_t q) {
    uint32_t R = r >> 1;
    uint32_t c = (q + ((r & 1) << 2)) ^ (R & 7);
    return R * 128 + c * 16;
}

// ---------------------------------------------------------------------------
// MLP GEMM, 32x32 tiles (full-chip grids). C = act(A@B + bias + res).
// 256 threads: 16x16 thread grid, 2x2 micro-tile. Split loader halves.
// Same per-output k-accumulation order as the old 64x64 kernel.
// ---------------------------------------------------------------------------
__global__ void __launch_bounds__(256)
gemm32(const float* __restrict__ A, const float* __restrict__ B,
       const float* __restrict__ bias, const float* __restrict__ res,
       float* __restrict__ C, __half* __restrict__ Ch,
       int M, int N, int K, int doRelu)
{
    __shared__ float As[16][32];   // [k][m]
    __shared__ float Bs[16][32];   // [k][n]

    const int tid = threadIdx.x;
    const int tig = tid >> 4, tjg = tid & 15;
    const int m0 = blockIdx.y * 32, n0 = blockIdx.x * 32;

    float acc[2][2] = {};

    for (int kk = 0; kk < K; kk += 16) {
        __syncthreads();
        if (tid < 128) {                       // A: 32 rows x 4 K-quads
            const int mr = tid >> 2, q = tid & 3;
            float4 av = *(const float4*)(A + (size_t)(m0 + mr) * K + kk + q * 4);
            As[q * 4 + 0][mr] = av.x; As[q * 4 + 1][mr] = av.y;
            As[q * 4 + 2][mr] = av.z; As[q * 4 + 3][mr] = av.w;
        } else {                               // B: 16 K-rows x 8 N-quads
            const int t = tid - 128;
            const int kr = t >> 3, q = t & 7;
            float4 bv = *(const float4*)(B + (size_t)(kk + kr) * N + n0 + q * 4);
            *(float4*)&Bs[kr][q * 4] = bv;
        }
        __syncthreads();
#pragma unroll
        for (int kc = 0; kc < 16; ++kc) {
            float2 a = *(const float2*)&As[kc][tig * 2];
            float2 b = *(const float2*)&Bs[kc][tjg * 2];
            acc[0][0] = fmaf(a.x, b.x, acc[0][0]);
            acc[0][1] = fmaf(a.x, b.y, acc[0][1]);
            acc[1][0] = fmaf(a.y, b.x, acc[1][0]);
            acc[1][1] = fmaf(a.y, b.y, acc[1][1]);
        }
    }

#pragma unroll
    for (int r = 0; r < 2; ++r) {
        const int gi = m0 + tig * 2 + r;
        const int gj = n0 + tjg * 2;
        float v0 = acc[r][0], v1 = acc[r][1];
        if (bias) { v0 += bias[gj]; v1 += bias[gj + 1]; }
        if (res) {
            v0 += res[(size_t)gi * N + gj];
            v1 += res[(size_t)gi * N + gj + 1];
        }
        if (doRelu) { v0 = fmaxf(v0, 0.0f); v1 = fmaxf(v1, 0.0f); }
        if (Ch) {
            Ch[(size_t)gi * N + gj]     = __float2half(v0);
            Ch[(size_t)gi * N + gj + 1] = __float2half(v1);
        } else {
            *(float2*)&C[(size_t)gi * N + gj] = make_float2(v0, v1);
        }
    }
}

// ---------------------------------------------------------------------------
// posX[k][j][c] = fp16(positive[j][c][k])  (transpose + convert)
// Tile 64r x 32k; 16B vectorized stores (full 128B sectors).
// ---------------------------------------------------------------------------
__global__ void __launch_bounds__(256)
possplit_kernel(const float* __restrict__ in, __half* __restrict__ out)
{
    __shared__ float tile[64][33];
    const int rbase = blockIdx.x * 64;
    const int kbase = blockIdx.y * 32;
    const int tx = threadIdx.x & 31, ty = threadIdx.x >> 5;

#pragma unroll
    for (int m = 0; m < 8; ++m) {
        int r = rbase + ty + m * 8;
        tile[ty + m * 8][tx] = __ldcs(&in[(size_t)r * 256 + kbase + tx]);
    }
    __syncthreads();

    const int t   = threadIdx.x;
    const int kk  = t >> 3;
    const int rr0 = (t & 7) * 8;
    const int k   = kbase + kk;
    const int rg  = rbase + rr0;
    const int j   = rg >> 8, c = rg & 255;

    __half h[8];
#pragma unroll
    for (int e = 0; e < 8; ++e) h[e] = __float2half(tile[rr0 + e][kk]);
    *(uint4*)&out[((size_t)k * BSZ + j) * KP + c] = *(const uint4*)h;
}

// ---------------------------------------------------------------------------
// HMMA contrast kernel (R13 structure). CTA = (k, 32-row i-tile), j=512,
// K=256. A preloaded once (8 chunks x 2KB); 8 warp-private B rings
// (3 stages x 4KB). No CTA barriers in the mainloop. Load issued before wait.
// ---------------------------------------------------------------------------
#define OF_BSL   16384                  // B slices after A region
#define CT_SMEM  (16384 + 8 * 3 * 4096) // 114688 -> 2 CTAs/SM

__global__ void __launch_bounds__(256, 2)
contrast_mma(const __half* __restrict__ predX,
             const __half* __restrict__ posX,
             float* __restrict__ out)
{
    extern __shared__ char smem[];
    const uint32_t sb = smem_u32(smem);
    const int tid = threadIdx.x;
    const int wid = tid >> 5, lid = tid & 31;
    const int k  = blockIdx.x >> 4;
    const int i0 = (blockIdx.x & 15) << 5;

    const char* Ab = (const char*)(predX + (size_t)i0 * KP);
    const char* Bw = (const char*)(posX + ((size_t)k * BSZ + wid * 64) * KP);

    float acc[16][4];   // tile t = mi*8 + njp*2 + hb
#pragma unroll
    for (int t = 0; t < 16; ++t) {
        acc[t][0] = 0.f; acc[t][1] = 0.f; acc[t][2] = 0.f; acc[t][3] = 0.f;
    }

    // ---- prologue: load ALL of A (32 rows x 256 K = 16KB, 8 chunk blocks)
    {
        const int half = tid >> 7, h = tid & 127;
        const int r = h >> 2, q = h & 3;
#pragma unroll
        for (int p = 0; p < 4; ++p) {
            const int ch = p * 2 + half;
            cp16(sb + ch * 2048 + swz(r, q),
                 Ab + (size_t)r * (KP * 2) + ch * 64 + q * 16);
        }
        CP_COMMIT();                    // group 0 (per thread): A
    }

    // ---- warp-private B loader: 64 rows x 64B per chunk into own ring ----
    const int bl_r = lid >> 2, bl_q = lid & 3;
    const uint32_t sbB = sb + OF_BSL + wid * (3 * 4096);
    auto loadB = [&](int n) {
        const uint32_t st = sbB + (n % 3) * 4096;
        const size_t co = (size_t)n * 64 + bl_q * 16;
#pragma unroll
        for (int it = 0; it < 8; ++it) {
            const int row = bl_r + it * 8;
            cp16(st + swz(row, bl_q), Bw + (size_t)row * (KP * 2) + co);
        }
        CP_COMMIT();
    };

    loadB(0);
    loadB(1);
    CP_WAIT(2);          // groups retire in order: A complete
    __syncthreads();     // A visible CTA-wide

    const uint32_t lrow = (uint32_t)(lid & 15);
    const uint32_t lqq  = (uint32_t)(lid >> 4);

#pragma unroll 1
    for (int n = 0; n < NCHUNK; ++n) {
        // issue the prefetch FIRST, then wait; chunk n resident when:
        //   outstanding <= 2 (n+1, n+2 pending) after issuing n+2
        if (n + 2 < NCHUNK) { loadB(n + 2); CP_WAIT(2); }
        else if (n + 1 < NCHUNK) { CP_WAIT(1); }
        else { CP_WAIT(0); }
        __syncwarp();

        const uint32_t at = sb + n * 2048;
        const uint32_t bt = sbB + (n % 3) * 4096;

        // A fragments for this chunk (both ks halves)
        uint32_t a[2][2][4];
#pragma unroll
        for (int ks = 0; ks < 2; ++ks)
#pragma unroll
            for (int mi = 0; mi < 2; ++mi)
                ldmx4(a[ks][mi][0], a[ks][mi][1], a[ks][mi][2], a[ks][mi][3],
                      at + swz(mi * 16 + lrow, ks * 2 + lqq));

        // B fragments double-buffered across the 8 (ks,njp) steps
        uint32_t b[2][4];
        ldmx4(b[0][0], b[0][1], b[0][2], b[0][3], bt + swz(lrow, lqq));
#pragma unroll
        for (int f = 0; f < 8; ++f) {
            const int ks = f >> 2, njp = f & 3;
            if (f < 7) {
                const int g = f + 1, gks = g >> 2, gnjp = g & 3;
                ldmx4(b[g & 1][0], b[g & 1][1], b[g & 1][2], b[g & 1][3],
                      bt + swz(gnjp * 16 + lrow, gks * 2 + lqq));
            }
            const uint32_t* bb = b[f & 1];
#pragma unroll
            for (int mi = 0; mi < 2; ++mi) {
                mma16816(acc[mi * 8 + njp * 2 + 0],
                         a[ks][mi][0], a[ks][mi][1], a[ks][mi][2], a[ks][mi][3],
                         bb[0], bb[2]);
                mma16816(acc[mi * 8 + njp * 2 + 1],
                         a[ks][mi][0], a[ks][mi][1], a[ks][mi][2], a[ks][mi][3],
                         bb[1], bb[3]);
            }
        }
    }

    // ---- fused row-max: every warp covers all 32 i rows, distinct j ----
    float mx0[2], mx1[2];
#pragma unroll
    for (int mi = 0; mi < 2; ++mi) {
        mx0[mi] = -3.402823466e38f;
        mx1[mi] = -3.402823466e38f;
#pragma unroll
        for (int nj = 0; nj < 8; ++nj) {
            const float* c = acc[mi * 8 + nj];
            mx0[mi] = fmaxf(mx0[mi], fmaxf(c[0], c[1]));
            mx1[mi] = fmaxf(mx1[mi], fmaxf(c[2], c[3]));
        }
        mx0[mi] = fmaxf(mx0[mi], __shfl_xor_sync(0xffffffffu, mx0[mi], 1));
        mx0[mi] = fmaxf(mx0[mi], __shfl_xor_sync(0xffffffffu, mx0[mi], 2));
        mx1[mi] = fmaxf(mx1[mi], __shfl_xor_sync(0xffffffffu, mx1[mi], 1));
        mx1[mi] = fmaxf(mx1[mi], __shfl_xor_sync(0xffffffffu, mx1[mi], 2));
    }

    __syncthreads();                 // ALL warps done with mainloop SMEM
    float* rmax = (float*)smem;      // reuse A region: [8 warps][32 rows]
    const int tr = lid >> 2;         // 0..7
    if ((lid & 3) == 0) {
#pragma unroll
        for (int mi = 0; mi < 2; ++mi) {
            rmax[wid * 32 + mi * 16 + tr]     = mx0[mi];
            rmax[wid * 32 + mi * 16 + 8 + tr] = mx1[mi];
        }
    }
    __syncthreads();

    float m0[2], m1[2];
#pragma unroll
    for (int mi = 0; mi < 2; ++mi) {
        float a0 = -3.402823466e38f, a1 = -3.402823466e38f;
#pragma unroll
        for (int w = 0; w < 8; ++w) {
            a0 = fmaxf(a0, rmax[w * 32 + mi * 16 + tr]);
            a1 = fmaxf(a1, rmax[w * 32 + mi * 16 + 8 + tr]);
        }
        m0[mi] = a0; m1[mi] = a1;
    }

    // ---- subtract + streaming store (evict-first: keep posX resident) ----
    const size_t obase = ((size_t)k * BSZ + i0) * BSZ + wid * 64 + (lid & 3) * 2;
#pragma unroll
    for (int mi = 0; mi < 2; ++mi) {
        float* o0 = out + obase + (size_t)(mi * 16 + tr) * BSZ;
        float* o1 = o0 + (size_t)8 * BSZ;
#pragma unroll
        for (int nj = 0; nj < 8; ++nj) {
            const float* c = acc[mi * 8 + nj];
            __stcs((float2*)(o0 + nj * 8), make_float2(c[0] - m0[mi], c[1] - m0[mi]));
            __stcs((float2*)(o1 + nj * 8), make_float2(c[2] - m1[mi], c[3] - m1[mi]));
        }
    }
}

// ---------------------------------------------------------------------------
// Launch
// ---------------------------------------------------------------------------
extern "C" void kernel_launch(void* const* d_in, const int* in_sizes, int n_in,
                              void* d_out, int out_size)
{
    const float* anchor   = (const float*)d_in[0];
    const float* positive = (const float*)d_in[1];
    const float* W1       = (const float*)d_in[2];
    const float* b1       = (const float*)d_in[3];
    const float* W2       = (const float*)d_in[4];
    const float* b2       = (const float*)d_in[5];
    const float* Wc       = (const float*)d_in[6];
    float* out            = (float*)d_out;

    float *hp, *ap;
    __half *px, *qx;
    cudaGetSymbolAddress((void**)&hp, g_h);
    cudaGetSymbolAddress((void**)&ap, g_a);
    cudaGetSymbolAddress((void**)&qx, g_predX);
    cudaGetSymbolAddress((void**)&px, g_posX);

    cudaFuncSetAttribute(contrast_mma,
                         cudaFuncAttributeMaxDynamicSharedMemorySize, CT_SMEM);

    // MLP chain (fp32, full-chip 32x32 tiling); 3rd GEMM writes fp16 predX
    gemm32<<<dim3(HIDDEN / 32, BSZ / 32), 256>>>(
        anchor, W1, b1, nullptr, hp, nullptr, BSZ, HIDDEN, LATENT, 1);
    gemm32<<<dim3(LATENT / 32, BSZ / 32), 256>>>(
        hp, W2, b2, anchor, ap, nullptr, BSZ, LATENT, HIDDEN, 0);
    gemm32<<<dim3(LATENT / 32, BSZ / 32), 256>>>(
        ap, Wc, nullptr, nullptr, nullptr, qx, BSZ, LATENT, LATENT, 0);

    // fp16 transpose prep (vectorized stores)
    possplit_kernel<<<dim3((BSZ * 256) / 64, HW / 32), dim3(256)>>>(positive, px);

    // HMMA contrast GEMM + fused rowmax (2 CTAs/SM, barrier-free mainloop)
    contrast_mma<<<HW * 16, 256, CT_SMEM>>>(qx, px, out);
}

// round 16
// speedup vs baseline: 1.1583x; 1.0600x over previous
#include <cuda_runtime.h>
#include <cuda_bf16.h>
#include <cuda_fp16.h>
#include <cstdint>
#include <cstddef>

// ---------------------------------------------------------------------------
// Shapes: B=512, LATENT=LOCAL=256, HIDDEN=512, HW=256
// out[k][i][j] = sum_c pred[i][c] * positive[j][c][k]  - rowmax_j
// R16: R15 contrast kernel (unchanged, best) + PREP FUSION:
//   each MLP GEMM launch co-schedules 1/3 of the possplit (transpose+fp16)
//   blocks via blockIdx dispatch, overlapping the independent possplit work
//   with the dependent MLP chain. Prep: ~42us serialized -> ~31us.
// ---------------------------------------------------------------------------

#define BSZ     512
#define LATENT  256
#define HIDDEN  512
#define HW      256
#define KP      256
#define NCHUNK  (KP / 32)        // 8

#define POS_BLOCKS 16384         // 2048 r-tiles x 8 k-tiles

__device__ float   g_h[BSZ * HIDDEN];
__device__ float   g_a[BSZ * LATENT];
__device__ __half  g_predX[BSZ * KP];                 // 256 KB
__device__ __half  g_posX[(size_t)HW * BSZ * KP];     // 64 MB (fits in L2)

// ---------------------------------------------------------------------------
// PTX helpers (generic-target only: cp.async, ldmatrix, mma.sync)
// ---------------------------------------------------------------------------
__device__ __forceinline__ uint32_t smem_u32(const void* p) {
    uint32_t a;
    asm("{ .reg .u64 t; cvta.to.shared.u64 t, %1; cvt.u32.u64 %0, t; }"
        : "=r"(a) : "l"(p));
    return a;
}
__device__ __forceinline__ void cp16(uint32_t dst, const void* src) {
    asm volatile("cp.async.cg.shared.global [%0], [%1], 16;"
                 :: "r"(dst), "l"(src) : "memory");
}
#define CP_COMMIT() asm volatile("cp.async.commit_group;" ::: "memory")
#define CP_WAIT(N)  asm volatile("cp.async.wait_group %0;" :: "n"(N) : "memory")

__device__ __forceinline__ void ldmx4(uint32_t& r0, uint32_t& r1,
                                      uint32_t& r2, uint32_t& r3,
                                      uint32_t addr) {
    asm volatile("ldmatrix.sync.aligned.m8n8.x4.shared.b16 {%0,%1,%2,%3}, [%4];"
                 : "=r"(r0), "=r"(r1), "=r"(r2), "=r"(r3) : "r"(addr));
}
__device__ __forceinline__ void mma16816(float* c,
                                         uint32_t a0, uint32_t a1,
                                         uint32_t a2, uint32_t a3,
                                         uint32_t b0, uint32_t b1) {
    asm volatile("mma.sync.aligned.m16n8k16.row.col.f32.f16.f16.f32 "
                 "{%0,%1,%2,%3}, {%4,%5,%6,%7}, {%8,%9}, {%0,%1,%2,%3};"
                 : "+f"(c[0]), "+f"(c[1]), "+f"(c[2]), "+f"(c[3])
                 : "r"(a0), "r"(a1), "r"(a2), "r"(a3), "r"(b0), "r"(b1));
}

// SW128 over 64B logical rows: row r, quad q (16B units, q=0..3).
__device__ __forceinline__ uint32_t swz(uint32_t r, uint32_t q) {
    uint32_t R = r >> 1;
    uint32_t c = (q + ((r & 1) << 2)) ^ (R & 7);
    return R * 128 + c * 16;
}

// ---------------------------------------------------------------------------
// Fused prep kernel: blocks [0, gemmG) run one MLP GEMM stage (32x32 tiles,
// same accumulation order as R15); blocks [gemmG, gemmG+posCount) run a
// slice of the possplit transpose (64r x 32k tiles, 16B vector stores).
// ---------------------------------------------------------------------------
__global__ void __launch_bounds__(256)
prep_fused(const float* __restrict__ A, const float* __restrict__ B,
           const float* __restrict__ bias, const float* __restrict__ res,
           float* __restrict__ C, __half* __restrict__ Ch,
           int M, int N, int K, int doRelu,
           int gemmBX, int gemmG,
           const float* __restrict__ pin, __half* __restrict__ pout,
           int posBase)
{
    __shared__ char smraw[64 * 33 * 4];   // max(gemm 4KB, possplit 8.25KB)
    const int tid = threadIdx.x;

    if ((int)blockIdx.x < gemmG) {
        // ---------------- GEMM stage ----------------
        float (*As)[32] = (float(*)[32])smraw;          // [16][32]
        float (*Bs)[32] = (float(*)[32])(smraw + 2048); // [16][32]

        const int bx = blockIdx.x % gemmBX, by = blockIdx.x / gemmBX;
        const int tig = tid >> 4, tjg = tid & 15;
        const int m0 = by * 32, n0 = bx * 32;

        float acc[2][2] = {};

        for (int kk = 0; kk < K; kk += 16) {
            __syncthreads();
            if (tid < 128) {                       // A: 32 rows x 4 K-quads
                const int mr = tid >> 2, q = tid & 3;
                float4 av = *(const float4*)(A + (size_t)(m0 + mr) * K + kk + q * 4);
                As[q * 4 + 0][mr] = av.x; As[q * 4 + 1][mr] = av.y;
                As[q * 4 + 2][mr] = av.z; As[q * 4 + 3][mr] = av.w;
            } else {                               // B: 16 K-rows x 8 N-quads
                const int t = tid - 128;
                const int kr = t >> 3, q = t & 7;
                float4 bv = *(const float4*)(B + (size_t)(kk + kr) * N + n0 + q * 4);
                *(float4*)&Bs[kr][q * 4] = bv;
            }
            __syncthreads();
#pragma unroll
            for (int kc = 0; kc < 16; ++kc) {
                float2 a = *(const float2*)&As[kc][tig * 2];
                float2 b = *(const float2*)&Bs[kc][tjg * 2];
                acc[0][0] = fmaf(a.x, b.x, acc[0][0]);
                acc[0][1] = fmaf(a.x, b.y, acc[0][1]);
                acc[1][0] = fmaf(a.y, b.x, acc[1][0]);
                acc[1][1] = fmaf(a.y, b.y, acc[1][1]);
            }
        }

#pragma unroll
        for (int r = 0; r < 2; ++r) {
            const int gi = m0 + tig * 2 + r;
            const int gj = n0 + tjg * 2;
            float v0 = acc[r][0], v1 = acc[r][1];
            if (bias) { v0 += bias[gj]; v1 += bias[gj + 1]; }
            if (res) {
                v0 += res[(size_t)gi * N + gj];
                v1 += res[(size_t)gi * N + gj + 1];
            }
            if (doRelu) { v0 = fmaxf(v0, 0.0f); v1 = fmaxf(v1, 0.0f); }
            if (Ch) {
                Ch[(size_t)gi * N + gj]     = __float2half(v0);
                Ch[(size_t)gi * N + gj + 1] = __float2half(v1);
            } else {
                *(float2*)&C[(size_t)gi * N + gj] = make_float2(v0, v1);
            }
        }
    } else {
        // ---------------- possplit slice ----------------
        float (*tile)[33] = (float(*)[33])smraw;        // [64][33]

        const int pb = posBase + ((int)blockIdx.x - gemmG);
        const int rbase = (pb & 2047) * 64;
        const int kbase = (pb >> 11) * 32;
        const int tx = tid & 31, ty = tid >> 5;

#pragma unroll
        for (int m = 0; m < 8; ++m) {
            int r = rbase + ty + m * 8;
            tile[ty + m * 8][tx] = __ldcs(&pin[(size_t)r * 256 + kbase + tx]);
        }
        __syncthreads();

        const int kk  = tid >> 3;
        const int rr0 = (tid & 7) * 8;
        const int k   = kbase + kk;
        const int rg  = rbase + rr0;
        const int j   = rg >> 8, c = rg & 255;

        __half h[8];
#pragma unroll
        for (int e = 0; e < 8; ++e) h[e] = __float2half(tile[rr0 + e][kk]);
        *(uint4*)&pout[((size_t)k * BSZ + j) * KP + c] = *(const uint4*)h;
    }
}

// ---------------------------------------------------------------------------
// HMMA contrast kernel (R15/R13 structure, unchanged — best so far).
// CTA = (k, 32-row i-tile), j=512, K=256. A preloaded once; 8 warp-private
// 3-stage B rings; no CTA barriers in the mainloop; prefetch before wait.
// ---------------------------------------------------------------------------
#define OF_BSL   16384                  // B slices after A region
#define CT_SMEM  (16384 + 8 * 3 * 4096) // 114688 -> 2 CTAs/SM

__global__ void __launch_bounds__(256, 2)
contrast_mma(const __half* __restrict__ predX,
             const __half* __restrict__ posX,
             float* __restrict__ out)
{
    extern __shared__ char smem[];
    const uint32_t sb = smem_u32(smem);
    const int tid = threadIdx.x;
    const int wid = tid >> 5, lid = tid & 31;
    const int k  = blockIdx.x >> 4;
    const int i0 = (blockIdx.x & 15) << 5;

    const char* Ab = (const char*)(predX + (size_t)i0 * KP);
    const char* Bw = (const char*)(posX + ((size_t)k * BSZ + wid * 64) * KP);

    float acc[16][4];   // tile t = mi*8 + njp*2 + hb
#pragma unroll
    for (int t = 0; t < 16; ++t) {
        acc[t][0] = 0.f; acc[t][1] = 0.f; acc[t][2] = 0.f; acc[t][3] = 0.f;
    }

    // ---- prologue: load ALL of A (32 rows x 256 K = 16KB, 8 chunk blocks)
    {
        const int half = tid >> 7, h = tid & 127;
        const int r = h >> 2, q = h & 3;
#pragma unroll
        for (int p = 0; p < 4; ++p) {
            const int ch = p * 2 + half;
            cp16(sb + ch * 2048 + swz(r, q),
                 Ab + (size_t)r * (KP * 2) + ch * 64 + q * 16);
        }
        CP_COMMIT();                    // group 0 (per thread): A
    }

    // ---- warp-private B loader: 64 rows x 64B per chunk into own ring ----
    const int bl_r = lid >> 2, bl_q = lid & 3;
    const uint32_t sbB = sb + OF_BSL + wid * (3 * 4096);
    auto loadB = [&](int n) {
        const uint32_t st = sbB + (n % 3) * 4096;
        const size_t co = (size_t)n * 64 + bl_q * 16;
#pragma unroll
        for (int it = 0; it < 8; ++it) {
            const int row = bl_r + it * 8;
            cp16(st + swz(row, bl_q), Bw + (size_t)row * (KP * 2) + co);
        }
        CP_COMMIT();
    };

    loadB(0);
    loadB(1);
    CP_WAIT(2);          // groups retire in order: A complete
    __syncthreads();     // A visible CTA-wide

    const uint32_t lrow = (uint32_t)(lid & 15);
    const uint32_t lqq  = (uint32_t)(lid >> 4);

#pragma unroll 1
    for (int n = 0; n < NCHUNK; ++n) {
        // issue the prefetch FIRST, then wait
        if (n + 2 < NCHUNK) { loadB(n + 2); CP_WAIT(2); }
        else if (n + 1 < NCHUNK) { CP_WAIT(1); }
        else { CP_WAIT(0); }
        __syncwarp();

        const uint32_t at = sb + n * 2048;
        const uint32_t bt = sbB + (n % 3) * 4096;

        // A fragments for this chunk (both ks halves)
        uint32_t a[2][2][4];
#pragma unroll
        for (int ks = 0; ks < 2; ++ks)
#pragma unroll
            for (int mi = 0; mi < 2; ++mi)
                ldmx4(a[ks][mi][0], a[ks][mi][1], a[ks][mi][2], a[ks][mi][3],
                      at + swz(mi * 16 + lrow, ks * 2 + lqq));

        // B fragments double-buffered across the 8 (ks,njp) steps
        uint32_t b[2][4];
        ldmx4(b[0][0], b[0][1], b[0][2], b[0][3], bt + swz(lrow, lqq));
#pragma unroll
        for (int f = 0; f < 8; ++f) {
            const int ks = f >> 2, njp = f & 3;
            if (f < 7) {
                const int g = f + 1, gks = g >> 2, gnjp = g & 3;
                ldmx4(b[g & 1][0], b[g & 1][1], b[g & 1][2], b[g & 1][3],
                      bt + swz(gnjp * 16 + lrow, gks * 2 + lqq));
            }
            const uint32_t* bb = b[f & 1];
#pragma unroll
            for (int mi = 0; mi < 2; ++mi) {
                mma16816(acc[mi * 8 + njp * 2 + 0],
                         a[ks][mi][0], a[ks][mi][1], a[ks][mi][2], a[ks][mi][3],
                         bb[0], bb[2]);
                mma16816(acc[mi * 8 + njp * 2 + 1],
                         a[ks][mi][0], a[ks][mi][1], a[ks][mi][2], a[ks][mi][3],
                         bb[1], bb[3]);
            }
        }
    }

    // ---- fused row-max: every warp covers all 32 i rows, distinct j ----
    float mx0[2], mx1[2];
#pragma unroll
    for (int mi = 0; mi < 2; ++mi) {
        mx0[mi] = -3.402823466e38f;
        mx1[mi] = -3.402823466e38f;
#pragma unroll
        for (int nj = 0; nj < 8; ++nj) {
            const float* c = acc[mi * 8 + nj];
            mx0[mi] = fmaxf(mx0[mi], fmaxf(c[0], c[1]));
            mx1[mi] = fmaxf(mx1[mi], fmaxf(c[2], c[3]));
        }
        mx0[mi] = fmaxf(mx0[mi], __shfl_xor_sync(0xffffffffu, mx0[mi], 1));
        mx0[mi] = fmaxf(mx0[mi], __shfl_xor_sync(0xffffffffu, mx0[mi], 2));
        mx1[mi] = fmaxf(mx1[mi], __shfl_xor_sync(0xffffffffu, mx1[mi], 1));
        mx1[mi] = fmaxf(mx1[mi], __shfl_xor_sync(0xffffffffu, mx1[mi], 2));
    }

    __syncthreads();                 // ALL warps done with mainloop SMEM
    float* rmax = (float*)smem;      // reuse A region: [8 warps][32 rows]
    const int tr = lid >> 2;         // 0..7
    if ((lid & 3) == 0) {
#pragma unroll
        for (int mi = 0; mi < 2; ++mi) {
            rmax[wid * 32 + mi * 16 + tr]     = mx0[mi];
            rmax[wid * 32 + mi * 16 + 8 + tr] = mx1[mi];
        }
    }
    __syncthreads();

    float m0[2], m1[2];
#pragma unroll
    for (int mi = 0; mi < 2; ++mi) {
        float a0 = -3.402823466e38f, a1 = -3.402823466e38f;
#pragma unroll
        for (int w = 0; w < 8; ++w) {
            a0 = fmaxf(a0, rmax[w * 32 + mi * 16 + tr]);
            a1 = fmaxf(a1, rmax[w * 32 + mi * 16 + 8 + tr]);
        }
        m0[mi] = a0; m1[mi] = a1;
    }

    // ---- subtract + streaming store (evict-first: keep posX resident) ----
    const size_t obase = ((size_t)k * BSZ + i0) * BSZ + wid * 64 + (lid & 3) * 2;
#pragma unroll
    for (int mi = 0; mi < 2; ++mi) {
        float* o0 = out + obase + (size_t)(mi * 16 + tr) * BSZ;
        float* o1 = o0 + (size_t)8 * BSZ;
#pragma unroll
        for (int nj = 0; nj < 8; ++nj) {
            const float* c = acc[mi * 8 + nj];
            __stcs((float2*)(o0 + nj * 8), make_float2(c[0] - m0[mi], c[1] - m0[mi]));
            __stcs((float2*)(o1 + nj * 8), make_float2(c[2] - m1[mi], c[3] - m1[mi]));
        }
    }
}

// ---------------------------------------------------------------------------
// Launch
// ---------------------------------------------------------------------------
extern "C" void kernel_launch(void* const* d_in, const int* in_sizes, int n_in,
                              void* d_out, int out_size)
{
    const float* anchor   = (const float*)d_in[0];
    const float* positive = (const float*)d_in[1];
    const float* W1       = (const float*)d_in[2];
    const float* b1       = (const float*)d_in[3];
    const float* W2       = (const float*)d_in[4];
    const float* b2       = (const float*)d_in[5];
    const float* Wc       = (const float*)d_in[6];
    float* out            = (float*)d_out;

    float *hp, *ap;
    __half *px, *qx;
    cudaGetSymbolAddress((void**)&hp, g_h);
    cudaGetSymbolAddress((void**)&ap, g_a);
    cudaGetSymbolAddress((void**)&qx, g_predX);
    cudaGetSymbolAddress((void**)&px, g_posX);

    cudaFuncSetAttribute(contrast_mma,
                         cudaFuncAttributeMaxDynamicSharedMemorySize, CT_SMEM);

    // possplit slice bounds (thirds of 16384)
    const int s0 = 5462, s1 = 5462, s2 = POS_BLOCKS - s0 - s1;   // 5460

    // Stage 1: h = relu(anchor@W1 + b1)  [grid 16x16=256] + possplit slice 0
    {
        const int gBX = HIDDEN / 32, gG = gBX * (BSZ / 32);
        prep_fused<<<gG + s0, 256>>>(anchor, W1, b1, nullptr, hp, nullptr,
                                     BSZ, HIDDEN, LATENT, 1,
                                     gBX, gG, positive, px, 0);
    }
    // Stage 2: a = anchor + h@W2 + b2   [grid 8x16=128] + possplit slice 1
    {
        const int gBX = LATENT / 32, gG = gBX * (BSZ / 32);
        prep_fused<<<gG + s1, 256>>>(hp, W2, b2, anchor, ap, nullptr,
                                     BSZ, LATENT, HIDDEN, 0,
                                     gBX, gG, positive, px, s0);
    }
    // Stage 3: predX = fp16(a@Wc)       [grid 8x16=128] + possplit slice 2
    {
        const int gBX = LATENT / 32, gG = gBX * (BSZ / 32);
        prep_fused<<<gG + s2, 256>>>(ap, Wc, nullptr, nullptr, nullptr, qx,
                                     BSZ, LATENT, LATENT, 0,
                                     gBX, gG, positive, px, s0 + s1);
    }

    // HMMA contrast GEMM + fused rowmax (2 CTAs/SM, barrier-free mainloop)
    contrast_mma<<<HW * 16, 256, CT_SMEM>>>(qx, px, out);
}